// round 1
// baseline (speedup 1.0000x reference)
#include <cuda_runtime.h>
#include <cstdint>

#define BOND_CUTOFF 3.6f
#define N_MAX 8192

// Static scratch: packed positions (x,y,z,pad). 8192 * 16 B = 128 KB.
__device__ float4 g_pos[N_MAX];

// ---------------------------------------------------------------------------
// Kernel 1: pack stride-7 input into contiguous float4 array.
// ---------------------------------------------------------------------------
__global__ void pack_pos_kernel(const float* __restrict__ x, int n) {
    int j = blockIdx.x * blockDim.x + threadIdx.x;
    if (j < n) {
        const float* p = x + (size_t)j * 7;
        g_pos[j] = make_float4(p[0], p[1], p[2], 0.0f);
    }
}

// ---------------------------------------------------------------------------
// Kernel 2: thresholded L1 distance matrix.
// Block: 256 threads. Tile: TI=16 rows x TJ=1024 cols.
// Each thread owns 4 consecutive columns (held in registers), loops over the
// 16 rows, writes one float4 per row -> fully coalesced 128-bit stores.
// ---------------------------------------------------------------------------
#define TI 16
#define TJ 1024

__global__ __launch_bounds__(256, 8)
void graph_kernel(float* __restrict__ out, int n) {
    const int t  = threadIdx.x;
    const int j0 = blockIdx.x * TJ + t * 4;   // first of this thread's 4 cols
    const int i0 = blockIdx.y * TI;

    // Load this thread's 4 column positions into registers (L1-resident).
    float4 c0 = g_pos[j0 + 0];
    float4 c1 = g_pos[j0 + 1];
    float4 c2 = g_pos[j0 + 2];
    float4 c3 = g_pos[j0 + 3];

    float* orow = out + (size_t)i0 * n + (size_t)(blockIdx.x * TJ) + (size_t)t * 4;

#pragma unroll
    for (int r = 0; r < TI; r++) {
        // Broadcast load of row position (one request per warp, L1 hit).
        float4 pi = g_pos[i0 + r];

        float4 res;
        {
            float dx = pi.x - c0.x, dy = pi.y - c0.y, dz = pi.z - c0.z;
            float d = (fabsf(dx) + fabsf(dy)) + fabsf(dz);
            res.x = (d <= BOND_CUTOFF) ? 1.0f : 0.0f;
        }
        {
            float dx = pi.x - c1.x, dy = pi.y - c1.y, dz = pi.z - c1.z;
            float d = (fabsf(dx) + fabsf(dy)) + fabsf(dz);
            res.y = (d <= BOND_CUTOFF) ? 1.0f : 0.0f;
        }
        {
            float dx = pi.x - c2.x, dy = pi.y - c2.y, dz = pi.z - c2.z;
            float d = (fabsf(dx) + fabsf(dy)) + fabsf(dz);
            res.z = (d <= BOND_CUTOFF) ? 1.0f : 0.0f;
        }
        {
            float dx = pi.x - c3.x, dy = pi.y - c3.y, dz = pi.z - c3.z;
            float d = (fabsf(dx) + fabsf(dy)) + fabsf(dz);
            res.w = (d <= BOND_CUTOFF) ? 1.0f : 0.0f;
        }

        *reinterpret_cast<float4*>(orow) = res;
        orow += n;
    }
}

// ---------------------------------------------------------------------------
// Fallback for shapes that don't tile evenly (defensive; N=8192 does).
// ---------------------------------------------------------------------------
__global__ void graph_kernel_generic(float* __restrict__ out, int n) {
    int j = blockIdx.x * blockDim.x + threadIdx.x;
    int i = blockIdx.y;
    if (i < n && j < n) {
        float4 pi = g_pos[i];
        float4 pj = g_pos[j];
        float d = (fabsf(pi.x - pj.x) + fabsf(pi.y - pj.y)) + fabsf(pi.z - pj.z);
        out[(size_t)i * n + j] = (d <= BOND_CUTOFF) ? 1.0f : 0.0f;
    }
}

extern "C" void kernel_launch(void* const* d_in, const int* in_sizes, int n_in,
                              void* d_out, int out_size) {
    const float* x = (const float*)d_in[0];
    int n = in_sizes[0] / 7;
    float* out = (float*)d_out;

    pack_pos_kernel<<<(n + 255) / 256, 256>>>(x, n);

    if (n > 0 && n <= N_MAX && (n % TJ) == 0 && (n % TI) == 0) {
        dim3 grid(n / TJ, n / TI);
        graph_kernel<<<grid, 256>>>(out, n);
    } else {
        dim3 grid((n + 255) / 256, n);
        graph_kernel_generic<<<grid, 256>>>(out, n);
    }
}